// round 1
// baseline (speedup 1.0000x reference)
#include <cuda_runtime.h>
#include <math.h>

#define NE    16
#define NB    512
#define NI    10
#define NF    3
#define NPROJ 7
#define NINP  4
#define NEMB  32
#define NTOT  79
#define NT    256
#define WSTR  80
#define NEB   (NE*NB)        // 8192
#define NCELL (NE*NB*NI)     // 81920

#define INV_SQRT_DEG 0.7071067811865476f

// Scratch: per-(e,b) effective weights:
// [0..28) w0e, [28..56) w1e, [56..63) b0e, [63..70) b1e,
// [70..77) wn_e * INV_SQRT_DEG, [77] bn_e, [78] (1-decay), [79] pad
__device__ float g_w[NEB * WSTR];

__device__ __forceinline__ float gelu_exact(float x) {
    return 0.5f * x * (1.0f + erff(x * 0.7071067811865476f));
}

template<int ROW0, int CNT>
__device__ __forceinline__ void do_group(const float* __restrict__ sWout,
                                         const float* __restrict__ sBout,
                                         const float* __restrict__ sBase,
                                         const float* h1,
                                         float* __restrict__ outp,
                                         float mul)
{
    float off[CNT];
    float on2 = 0.0f, rn2 = 0.0f;
    #pragma unroll
    for (int k = 0; k < CNT; k++) {
        const int o = ROW0 + k;
        float a = sBout[o];
        #pragma unroll
        for (int i = 0; i < NEMB; i++) a = fmaf(sWout[o*NEMB + i], h1[i], a);
        off[k] = a;
        on2 = fmaf(a, a, on2);
        const float w = sBase[ROW0 + k];
        rn2 = fmaf(w, w, rn2);
    }
    const float mx = fmaxf(sqrtf(rn2) * 0.5f, 0.01f);
    const float sc = fminf(mx / (sqrtf(on2) + 1e-8f), 1.0f);
    #pragma unroll
    for (int k = 0; k < CNT; k++)
        outp[ROW0 + k] = (sBase[ROW0 + k] + off[k] * sc) * mul;
}

// One thread per (e,b). 64 blocks of 128; block bi handles e = bi>>2, b-slice of 128.
__global__ void hyper_kernel(
    const float* __restrict__ emb,
    const float* __restrict__ w0, const float* __restrict__ w1,
    const float* __restrict__ b0, const float* __restrict__ b1,
    const float* __restrict__ wn, const float* __restrict__ bn,
    const float* __restrict__ damping,
    const float* __restrict__ hW_in, const float* __restrict__ hb_in,
    const float* __restrict__ hW_out, const float* __restrict__ hb_out)
{
    __shared__ float sWin[NEMB*NEMB];
    __shared__ float sBin[NEMB];
    __shared__ float sWout[NTOT*NEMB];
    __shared__ float sBout[NTOT];
    __shared__ float sBase[78];
    __shared__ float sOmd;

    const int e = blockIdx.x >> 2;
    const int b = ((blockIdx.x & 3) << 7) + threadIdx.x;

    for (int i = threadIdx.x; i < NEMB*NEMB; i += blockDim.x) sWin[i]  = hW_in[e*NEMB*NEMB + i];
    for (int i = threadIdx.x; i < NTOT*NEMB; i += blockDim.x) sWout[i] = hW_out[e*NTOT*NEMB + i];
    for (int i = threadIdx.x; i < NEMB; i += blockDim.x)      sBin[i]  = hb_in[e*NEMB + i];
    for (int i = threadIdx.x; i < NTOT; i += blockDim.x)      sBout[i] = hb_out[e*NTOT + i];
    for (int i = threadIdx.x; i < 28; i += blockDim.x) {
        sBase[i]      = w0[e*28 + i];
        sBase[28 + i] = w1[e*28 + i];
    }
    for (int i = threadIdx.x; i < NPROJ; i += blockDim.x) {
        sBase[56 + i] = b0[e*NPROJ + i];
        sBase[63 + i] = b1[e*NPROJ + i];
        sBase[70 + i] = wn[e*NPROJ + i];
    }
    if (threadIdx.x == 0) {
        sBase[77] = bn[e];
        sOmd = 1.0f - 1.0f / (1.0f + expf(-damping[e]));
    }
    __syncthreads();

    // embedding -> registers
    float er[NEMB];
    const float* ep = emb + (e*NB + b) * NEMB;
    #pragma unroll
    for (int i = 0; i < NEMB; i++) er[i] = ep[i];

    // h1 = gelu(W_in @ emb + b_in)
    float h1[NEMB];
    #pragma unroll
    for (int o = 0; o < NEMB; o++) {
        float a = sBin[o];
        #pragma unroll
        for (int i = 0; i < NEMB; i++) a = fmaf(sWin[o*NEMB + i], er[i], a);
        h1[o] = gelu_exact(a);
    }

    float* outp = g_w + (e*NB + b) * WSTR;

    do_group<0, 28>(sWout, sBout, sBase, h1, outp, 1.0f);      // w0e
    do_group<28, 28>(sWout, sBout, sBase, h1, outp, 1.0f);     // w1e
    do_group<56, 7>(sWout, sBout, sBase, h1, outp, 1.0f);      // b0e
    do_group<63, 7>(sWout, sBout, sBase, h1, outp, 1.0f);      // b1e
    do_group<70, 7>(sWout, sBout, sBase, h1, outp, INV_SQRT_DEG); // wn_e * 1/sqrt(2)
    do_group<77, 1>(sWout, sBout, sBase, h1, outp, 1.0f);      // bn_e

    outp[78] = sOmd;
    outp[79] = 0.0f;
}

// One thread per cell (e,b,i). 256 recurrent steps with all weights in registers.
__global__ void __launch_bounds__(256, 2) rnn_kernel(
    const float* __restrict__ x,
    const float* __restrict__ h0,
    float* __restrict__ out)
{
    const int cell = blockIdx.x * 256 + threadIdx.x;
    const int eb = cell / NI;

    float w[WSTR];
    const float4* wp = reinterpret_cast<const float4*>(g_w + eb * WSTR);
    #pragma unroll
    for (int q = 0; q < WSTR/4; q++) {
        float4 v = wp[q];
        w[4*q]   = v.x; w[4*q+1] = v.y;
        w[4*q+2] = v.z; w[4*q+3] = v.w;
    }

    float h = h0[cell];
    const float omd = w[78];   // 1 - decay
    const float bnv = w[77];   // bias_n effective

    const float* xp = x + (size_t)cell * NF;
    float*       op = out + cell;

    #pragma unroll 2
    for (int t = 0; t < NT; t++) {
        const float x0 = xp[0], x1 = xp[1], x2 = xp[2];
        float d = bnv;
        #pragma unroll
        for (int j = 0; j < NPROJ; j++) {
            float a = fmaf(w[4*j+3], h,
                      fmaf(w[4*j+2], x2,
                      fmaf(w[4*j+1], x1,
                      fmaf(w[4*j+0], x0, w[56+j]))));
            float c = fmaf(w[28+4*j+3], h,
                      fmaf(w[28+4*j+2], x2,
                      fmaf(w[28+4*j+1], x1,
                      fmaf(w[28+4*j+0], x0, w[63+j]))));
            d = fmaf(w[70+j], a * c, d);
        }
        h = fmaf(h, omd, d);
        *op = h;
        xp += NE*NB*NI*NF;   // next timestep
        op += NCELL;
    }
}

extern "C" void kernel_launch(void* const* d_in, const int* in_sizes, int n_in,
                              void* d_out, int out_size)
{
    const float* inputs    = (const float*)d_in[0];
    const float* h0        = (const float*)d_in[1];
    const float* embedding = (const float*)d_in[2];
    const float* w0        = (const float*)d_in[3];
    const float* w1        = (const float*)d_in[4];
    const float* b0        = (const float*)d_in[5];
    const float* b1        = (const float*)d_in[6];
    const float* wn        = (const float*)d_in[7];
    const float* bn        = (const float*)d_in[8];
    const float* damping   = (const float*)d_in[9];
    const float* hW_in     = (const float*)d_in[10];
    const float* hb_in     = (const float*)d_in[11];
    const float* hW_out    = (const float*)d_in[12];
    const float* hb_out    = (const float*)d_in[13];
    float* out = (float*)d_out;

    hyper_kernel<<<64, 128>>>(embedding, w0, w1, b0, b1, wn, bn, damping,
                              hW_in, hb_in, hW_out, hb_out);
    rnn_kernel<<<NCELL/256, 256>>>(inputs, h0, out);
}

// round 3
// speedup vs baseline: 1.9191x; 1.9191x over previous
#include <cuda_runtime.h>
#include <math.h>
#include <stdint.h>

#define NE    16
#define NB    512
#define NI    10
#define NF    3
#define NPROJ 7
#define NEMB  32
#define NTOT  79
#define NT    256
#define WSTR  80
#define NEB   (NE*NB)        // 8192
#define NCELL (NE*NB*NI)     // 81920
#define CHUNK 8
#define TPB   256

#define INV_SQRT_DEG 0.7071067811865476f

// Scratch: per-(e,b) effective weights, PAIRED layout for f32x2:
// [0..56)  : 28 pairs (w0e[j][i], w1e[j][i]) at 2*(4*j+i)
// [56..70) : 7 pairs (b0e[j], b1e[j])
// [70..77) : wn_e[j] * INV_SQRT_DEG
// [77] bn_e, [78] (1-decay), [79] pad
__device__ float g_w[NEB * WSTR];

__device__ __forceinline__ float gelu_exact(float x) {
    return 0.5f * x * (1.0f + erff(x * 0.7071067811865476f));
}

// ---------- f32x2 packed helpers ----------
__device__ __forceinline__ unsigned long long pack2(float lo, float hi) {
    unsigned long long r;
    asm("mov.b64 %0, {%1, %2};" : "=l"(r) : "f"(lo), "f"(hi));
    return r;
}
__device__ __forceinline__ void unpack2(float& lo, float& hi, unsigned long long v) {
    asm("mov.b64 {%0, %1}, %2;" : "=f"(lo), "=f"(hi) : "l"(v));
}
__device__ __forceinline__ unsigned long long fma2(unsigned long long a,
                                                   unsigned long long b,
                                                   unsigned long long c) {
    unsigned long long d;
    asm("fma.rn.f32x2 %0, %1, %2, %3;" : "=l"(d) : "l"(a), "l"(b), "l"(c));
    return d;
}

// ---------- hypernetwork ----------
template<int CNT>
__device__ __forceinline__ void do_group(const float* __restrict__ sWout,
                                         const float* __restrict__ sBout,
                                         const float* __restrict__ sBase,
                                         int row0,
                                         const float* h1,
                                         float* __restrict__ res)
{
    float on2 = 0.0f, rn2 = 0.0f;
    #pragma unroll
    for (int k = 0; k < CNT; k++) {
        const int o = row0 + k;
        float a = sBout[o];
        #pragma unroll
        for (int i = 0; i < NEMB; i++) a = fmaf(sWout[o*NEMB + i], h1[i], a);
        res[k] = a;
        on2 = fmaf(a, a, on2);
        const float w = sBase[o];
        rn2 = fmaf(w, w, rn2);
    }
    const float mx = fmaxf(sqrtf(rn2) * 0.5f, 0.01f);
    const float sc = fminf(mx / (sqrtf(on2) + 1e-8f), 1.0f);
    #pragma unroll
    for (int k = 0; k < CNT; k++)
        res[k] = sBase[row0 + k] + res[k] * sc;
}

__global__ void hyper_kernel(
    const float* __restrict__ emb,
    const float* __restrict__ w0, const float* __restrict__ w1,
    const float* __restrict__ b0, const float* __restrict__ b1,
    const float* __restrict__ wn, const float* __restrict__ bn,
    const float* __restrict__ damping,
    const float* __restrict__ hW_in, const float* __restrict__ hb_in,
    const float* __restrict__ hW_out, const float* __restrict__ hb_out)
{
    __shared__ float sWin[NEMB*NEMB];
    __shared__ float sBin[NEMB];
    __shared__ float sWout[NTOT*NEMB];
    __shared__ float sBout[NTOT];
    __shared__ float sBase[78];
    __shared__ float sOmd;

    const int e = blockIdx.x >> 2;
    const int b = ((blockIdx.x & 3) << 7) + threadIdx.x;

    for (int i = threadIdx.x; i < NEMB*NEMB; i += blockDim.x) sWin[i]  = hW_in[e*NEMB*NEMB + i];
    for (int i = threadIdx.x; i < NTOT*NEMB; i += blockDim.x) sWout[i] = hW_out[e*NTOT*NEMB + i];
    for (int i = threadIdx.x; i < NEMB; i += blockDim.x)      sBin[i]  = hb_in[e*NEMB + i];
    for (int i = threadIdx.x; i < NTOT; i += blockDim.x)      sBout[i] = hb_out[e*NTOT + i];
    for (int i = threadIdx.x; i < 28; i += blockDim.x) {
        sBase[i]      = w0[e*28 + i];
        sBase[28 + i] = w1[e*28 + i];
    }
    for (int i = threadIdx.x; i < NPROJ; i += blockDim.x) {
        sBase[56 + i] = b0[e*NPROJ + i];
        sBase[63 + i] = b1[e*NPROJ + i];
        sBase[70 + i] = wn[e*NPROJ + i];
    }
    if (threadIdx.x == 0) {
        sBase[77] = bn[e];
        sOmd = 1.0f - 1.0f / (1.0f + expf(-damping[e]));
    }
    __syncthreads();

    float er[NEMB];
    const float* ep = emb + (e*NB + b) * NEMB;
    #pragma unroll
    for (int i = 0; i < NEMB; i++) er[i] = ep[i];

    float h1[NEMB];
    #pragma unroll
    for (int o = 0; o < NEMB; o++) {
        float a = sBin[o];
        #pragma unroll
        for (int i = 0; i < NEMB; i++) a = fmaf(sWin[o*NEMB + i], er[i], a);
        h1[o] = gelu_exact(a);
    }

    float g0[28], g1[28], g2[7], g3[7], g4[7], g5[1];
    do_group<28>(sWout, sBout, sBase, 0,  h1, g0);   // w0e
    do_group<28>(sWout, sBout, sBase, 28, h1, g1);   // w1e
    do_group<7 >(sWout, sBout, sBase, 56, h1, g2);   // b0e
    do_group<7 >(sWout, sBout, sBase, 63, h1, g3);   // b1e
    do_group<7 >(sWout, sBout, sBase, 70, h1, g4);   // wn_e
    do_group<1 >(sWout, sBout, sBase, 77, h1, g5);   // bn_e

    float* outp = g_w + (e*NB + b) * WSTR;
    #pragma unroll
    for (int k = 0; k < 28; k++) {
        outp[2*k]     = g0[k];
        outp[2*k + 1] = g1[k];
    }
    #pragma unroll
    for (int j = 0; j < NPROJ; j++) {
        outp[56 + 2*j]     = g2[j];
        outp[56 + 2*j + 1] = g3[j];
        outp[70 + j]       = g4[j] * INV_SQRT_DEG;
    }
    outp[77] = g5[0];
    outp[78] = sOmd;
    outp[79] = 0.0f;
}

// ---------- cp.async helpers ----------
__device__ __forceinline__ void cp_async16(uint32_t saddr, const void* gaddr) {
    asm volatile("cp.async.cg.shared.global [%0], [%1], 16;\n"
                 :: "r"(saddr), "l"(gaddr));
}
__device__ __forceinline__ void cp_commit() {
    asm volatile("cp.async.commit_group;\n" ::: "memory");
}
template<int N>
__device__ __forceinline__ void cp_wait() {
    asm volatile("cp.async.wait_group %0;\n" :: "n"(N) : "memory");
}

// ---------- recurrent scan ----------
// One thread per cell. x staged through smem via cp.async double buffer.
__global__ void __launch_bounds__(TPB, 2) rnn_kernel(
    const float* __restrict__ x,
    const float* __restrict__ h0,
    float* __restrict__ out)
{
    // 2 buffers * 8 timesteps * 256 cells * 3 floats = 49152 B (static smem cap)
    __shared__ float sx[2][CHUNK * TPB * NF];

    const int tid  = threadIdx.x;
    const int cell = blockIdx.x * TPB + tid;
    const int eb   = cell / NI;

    // ---- load paired weights into registers ----
    unsigned long long wab[28];    // (w0,w1) pairs
    unsigned long long bb[NPROJ];  // (b0,b1) pairs
    float wn[NPROJ];
    {
        const unsigned long long* p =
            reinterpret_cast<const unsigned long long*>(g_w + (size_t)eb * WSTR);
        #pragma unroll
        for (int k = 0; k < 28; k++) wab[k] = p[k];
        #pragma unroll
        for (int k = 0; k < NPROJ; k++) bb[k] = p[28 + k];
    }
    const float* wrow = g_w + (size_t)eb * WSTR;
    #pragma unroll
    for (int j = 0; j < NPROJ; j++) wn[j] = wrow[70 + j];
    const float bnv = wrow[77];
    const float omd = wrow[78];

    float h = h0[cell];

    const float* gx = x + (size_t)blockIdx.x * TPB * NF;  // block's cell base
    float* op = out + cell;

    const uint32_t sbase = (uint32_t)__cvta_generic_to_shared(&sx[0][0]);
    const int xoff = 3 * tid;   // word offset of this thread's cell within a segment

    // bytes per timestep-segment for this block = 256*3*4 = 3072 (192 x 16B)
    // per chunk: 8 segments = 1536 x 16B; each thread issues 6 cp.async
    auto fill_chunk = [&](int c, int buf) {
        const uint32_t dbase = sbase + (uint32_t)buf * (CHUNK * TPB * NF * 4);
        #pragma unroll
        for (int k = 0; k < 6; k++) {
            const int q   = tid + k * TPB;        // 0..1535
            const int tt  = q / 192;
            const int rem = q - tt * 192;
            const float* src = gx + ((size_t)(c * CHUNK + tt)) * ((size_t)NCELL * NF)
                                  + rem * 4;
            cp_async16(dbase + (uint32_t)(tt * 3072 + rem * 16), src);
        }
        cp_commit();
    };

    fill_chunk(0, 0);

    const int NCHUNK = NT / CHUNK;   // 32
    for (int c = 0; c < NCHUNK; c++) {
        const int buf = c & 1;
        if (c + 1 < NCHUNK) {
            fill_chunk(c + 1, buf ^ 1);
            cp_wait<1>();
        } else {
            cp_wait<0>();
        }
        __syncthreads();

        const float* sb = &sx[buf][0];
        #pragma unroll
        for (int tt = 0; tt < CHUNK; tt++) {
            const float x0 = sb[tt * (TPB*NF) + xoff];
            const float x1 = sb[tt * (TPB*NF) + xoff + 1];
            const float x2 = sb[tt * (TPB*NF) + xoff + 2];

            const unsigned long long xx0 = pack2(x0, x0);
            const unsigned long long xx1 = pack2(x1, x1);
            const unsigned long long xx2 = pack2(x2, x2);
            const unsigned long long hh  = pack2(h, h);

            float d = bnv;
            #pragma unroll
            for (int j = 0; j < NPROJ; j++) {
                unsigned long long acc = bb[j];
                acc = fma2(wab[4*j + 0], xx0, acc);
                acc = fma2(wab[4*j + 1], xx1, acc);
                acc = fma2(wab[4*j + 2], xx2, acc);
                acc = fma2(wab[4*j + 3], hh,  acc);
                float a, cc;
                unpack2(a, cc, acc);
                d = fmaf(wn[j], a * cc, d);
            }
            h = fmaf(h, omd, d);
            *op = h;
            op += NCELL;
        }
        __syncthreads();   // buffer (buf) safe to overwrite at iter c+2
    }
}

extern "C" void kernel_launch(void* const* d_in, const int* in_sizes, int n_in,
                              void* d_out, int out_size)
{
    const float* inputs    = (const float*)d_in[0];
    const float* h0        = (const float*)d_in[1];
    const float* embedding = (const float*)d_in[2];
    const float* w0        = (const float*)d_in[3];
    const float* w1        = (const float*)d_in[4];
    const float* b0        = (const float*)d_in[5];
    const float* b1        = (const float*)d_in[6];
    const float* wn        = (const float*)d_in[7];
    const float* bn        = (const float*)d_in[8];
    const float* damping   = (const float*)d_in[9];
    const float* hW_in     = (const float*)d_in[10];
    const float* hb_in     = (const float*)d_in[11];
    const float* hW_out    = (const float*)d_in[12];
    const float* hb_out    = (const float*)d_in[13];
    float* out = (float*)d_out;

    hyper_kernel<<<64, 128>>>(embedding, w0, w1, b0, b1, wn, bn, damping,
                              hW_in, hb_in, hW_out, hb_out);
    rnn_kernel<<<NCELL/TPB, TPB>>>(inputs, h0, out);
}